// round 8
// baseline (speedup 1.0000x reference)
#include <cuda_runtime.h>

#define THREADS 256
#define IT 4                      // i-rows per thread (2 f32x2 packs)
#define I_TILE (THREADS * IT)     // 1024
#define J_TILE 128
#define MAXB 8192

__device__ double g_partial[MAXB];
__device__ int    g_done = 0;

typedef unsigned long long u64;

__device__ __forceinline__ float fast_lg2(float x) {
    float r; asm("lg2.approx.f32 %0, %1;" : "=f"(r) : "f"(x)); return r;
}
__device__ __forceinline__ u64 add2(u64 a, u64 b) {
    u64 r; asm("add.rn.f32x2 %0, %1, %2;" : "=l"(r) : "l"(a), "l"(b)); return r;
}
__device__ __forceinline__ u64 fma2(u64 a, u64 b, u64 c) {
    u64 r; asm("fma.rn.f32x2 %0, %1, %2, %3;" : "=l"(r) : "l"(a), "l"(b), "l"(c));
    return r;
}
__device__ __forceinline__ u64 pack2(float lo, float hi) {
    u64 r; asm("mov.b64 %0, {%1, %2};" : "=l"(r) : "f"(lo), "f"(hi)); return r;
}
__device__ __forceinline__ void unpack2(u64 v, float& lo, float& hi) {
    asm("mov.b64 {%0, %1}, %2;" : "=f"(lo), "=f"(hi) : "l"(v));
}
// Packed: e = 2^( a XOR signbit(s) ) per 32-bit half. LOP3 immLut 0x78 = a^(b&c).
__device__ __forceinline__ u64 ex2_pair(u64 a, u64 s) {
    u64 r;
    asm("{\n\t"
        ".reg .b32 al, ah, sl, sh;\n\t"
        ".reg .f32 f0, f1, g0, g1;\n\t"
        "mov.b64 {al, ah}, %1;\n\t"
        "mov.b64 {sl, sh}, %2;\n\t"
        "lop3.b32 al, al, sl, 0x80000000, 0x78;\n\t"
        "lop3.b32 ah, ah, sh, 0x80000000, 0x78;\n\t"
        "mov.b32 f0, al;\n\t"
        "mov.b32 f1, ah;\n\t"
        "ex2.approx.f32 g0, f0;\n\t"
        "ex2.approx.f32 g1, f1;\n\t"
        "mov.b64 %0, {g0, g1};\n\t"
        "}" : "=l"(r) : "l"(a), "l"(s));
    return r;
}
// Scalar fused: e = 2^( a XOR signbit(s) )
__device__ __forceinline__ float ex2s(float a, float s) {
    float r;
    asm("{\n\t"
        ".reg .b32 t;\n\t"
        ".reg .f32 f;\n\t"
        "lop3.b32 t, %1, %2, 0x80000000, 0x78;\n\t"
        "mov.b32 f, t;\n\t"
        "ex2.approx.f32 %0, f;\n\t"
        "}" : "=f"(r) : "r"(__float_as_uint(a)), "r"(__float_as_uint(s)));
    return r;
}
// Band: if (jgx > ig) prod = fma(prod, e, prod)
__device__ __forceinline__ void fma_if_gt(float& prod, float e, int jgx, int ig) {
    asm("{\n\t"
        ".reg .pred p;\n\t"
        "setp.gt.s32 p, %2, %3;\n\t"
        "@p fma.rn.f32 %0, %0, %1, %0;\n\t"
        "}" : "+f"(prod) : "f"(e), "r"(jgx), "r"(ig));
}

// Pair {i,j}: logsig(d) = -ln2 * lg2(1 + 2^arg),
//   arg = (pi - pj)*log2e XOR signbit(ti - tj).  Count analytic: n(n-1)/2.
__global__ __launch_bounds__(THREADS, 2)
void rankloss_kernel(const float* __restrict__ P, const float* __restrict__ T,
                     float* __restrict__ out, int n, int NTI, int NTJ,
                     double inv_neg_count) {
    const int tid = threadIdx.x;
    const int nb  = gridDim.x;

    // decode linear block id -> (I, J) over upper-triangle band
    int b = blockIdx.x, I = 0, J = 0;
    {
        int rem = b;
        for (int ii = 0; ii < NTI; ++ii) {
            int jmin = (ii * I_TILE) / J_TILE;
            int cntI = NTJ - jmin;
            if (rem < cntI) { I = ii; J = jmin + rem; break; }
            rem -= cntI;
        }
    }
    const int I0 = I * I_TILE;
    const int J0 = J * J_TILE;
    const bool dense = (J0 >= I0 + I_TILE) && (J0 + J_TILE <= n) && (I0 + I_TILE <= n);

    __shared__ float4 sj[J_TILE];     // (-tj, -tj, -pjs, -pjs)
    __shared__ double sred[THREADS];

    const float LOG2E = 1.4426950408889634f;

    if (tid < J_TILE) {
        int jg = J0 + tid;
        float nt = 0.0f, np = 0.0f;
        if (jg < n) { nt = -T[jg]; np = -(P[jg] * LOG2E); }
        sj[tid] = make_float4(nt, nt, np, np);
    }

    float pis[IT], tis[IT];
    int   igv[IT];
    #pragma unroll
    for (int r = 0; r < IT; ++r) {
        int ig = I0 + r * THREADS + tid;
        int g  = (ig < n) ? ig : 0;
        pis[r] = P[g] * LOG2E;
        tis[r] = T[g];
        igv[r] = ig;
    }
    const u64 t01 = pack2(tis[0], tis[1]);
    const u64 t23 = pack2(tis[2], tis[3]);
    const u64 p01 = pack2(pis[0], pis[1]);
    const u64 p23 = pack2(pis[2], pis[3]);
    const u64 ONE2 = 0x3F8000003F800000ull;   // (1.0f, 1.0f)
    __syncthreads();

    float acc = 0.0f;

    if (dense) {
        #pragma unroll 1
        for (int j = 0; j < J_TILE; j += 8) {
            u64 prod01 = ONE2, prod23 = ONE2;
            #pragma unroll
            for (int jj = 0; jj < 8; ++jj) {
                float4 v = sj[j + jj];             // one LDS.128
                u64 nt = pack2(v.x, v.y);
                u64 np = pack2(v.z, v.w);
                u64 s01 = add2(t01, nt);
                u64 s23 = add2(t23, nt);
                u64 a01 = add2(p01, np);
                u64 a23 = add2(p23, np);
                u64 e01 = ex2_pair(a01, s01);
                u64 e23 = ex2_pair(a23, s23);
                prod01 = fma2(prod01, e01, prod01);
                prod23 = fma2(prod23, e23, prod23);
            }
            float q0, q1, q2, q3;
            unpack2(prod01, q0, q1);
            unpack2(prod23, q2, q3);
            acc += fast_lg2(q0);
            acc += fast_lg2(q1);
            acc += fast_lg2(q2);
            acc += fast_lg2(q3);
        }
    } else {
        #pragma unroll 1
        for (int j = 0; j < J_TILE; j += 8) {
            float prod0 = 1.0f, prod1 = 1.0f, prod2 = 1.0f, prod3 = 1.0f;
            #pragma unroll
            for (int jj = 0; jj < 8; ++jj) {
                int jg  = J0 + j + jj;
                int jgx = (jg < n) ? jg : (int)0x80000000;   // never > any ig
                float4 v = sj[j + jj];
                float s0 = tis[0] + v.x, a0 = pis[0] + v.z;
                float s1 = tis[1] + v.x, a1 = pis[1] + v.z;
                float s2 = tis[2] + v.x, a2 = pis[2] + v.z;
                float s3 = tis[3] + v.x, a3 = pis[3] + v.z;
                float e0 = ex2s(a0, s0);
                float e1 = ex2s(a1, s1);
                float e2 = ex2s(a2, s2);
                float e3 = ex2s(a3, s3);
                fma_if_gt(prod0, e0, jgx, igv[0]);
                fma_if_gt(prod1, e1, jgx, igv[1]);
                fma_if_gt(prod2, e2, jgx, igv[2]);
                fma_if_gt(prod3, e3, jgx, igv[3]);
            }
            acc += fast_lg2(prod0);
            acc += fast_lg2(prod1);
            acc += fast_lg2(prod2);
            acc += fast_lg2(prod3);
        }
    }

    // block reduction (fixed order -> deterministic)
    sred[tid] = (double)acc;
    __syncthreads();
    #pragma unroll
    for (int s = THREADS / 2; s > 0; s >>= 1) {
        if (tid < s) sred[tid] += sred[tid + s];
        __syncthreads();
    }
    if (tid == 0) g_partial[blockIdx.x] = sred[0];

    // last-block finalize (fixed order -> deterministic)
    __shared__ int is_last;
    if (tid == 0) {
        __threadfence();
        int prev = atomicAdd(&g_done, 1);
        is_last = (prev == nb - 1) ? 1 : 0;
    }
    __syncthreads();
    if (is_last) {
        __threadfence();
        double s = 0.0;
        for (int i = tid; i < nb; i += THREADS) s += g_partial[i];
        sred[tid] = s;
        __syncthreads();
        #pragma unroll
        for (int k = THREADS / 2; k > 0; k >>= 1) {
            if (tid < k) sred[tid] += sred[tid + k];
            __syncthreads();
        }
        if (tid == 0) {
            out[0] = (float)(sred[0] * inv_neg_count);
            g_done = 0;   // reset for next graph replay
        }
    }
}

extern "C" void kernel_launch(void* const* d_in, const int* in_sizes, int n_in,
                              void* d_out, int out_size) {
    const float* predictions = (const float*)d_in[0];
    const float* targets     = (const float*)d_in[1];
    const int n = in_sizes[0];

    const int NTI = (n + I_TILE - 1) / I_TILE;   // 8 for n=8192
    const int NTJ = (n + J_TILE - 1) / J_TILE;   // 64
    int nb = 0;
    for (int ii = 0; ii < NTI; ++ii) {
        int jmin = (ii * I_TILE) / J_TILE;
        nb += NTJ - jmin;                        // 288 for n=8192
    }
    const double count = 0.5 * (double)n * (double)(n - 1);
    const double inv_neg_count = -0.6931471805599453 / count;

    rankloss_kernel<<<nb, THREADS>>>(predictions, targets, (float*)d_out,
                                     n, NTI, NTJ, inv_neg_count);
}

// round 9
// speedup vs baseline: 1.0855x; 1.0855x over previous
#include <cuda_runtime.h>

#define THREADS 256
#define IT 4                      // i-rows per thread
#define I_TILE (THREADS * IT)     // 1024
#define J_TILE 64
#define MAXB 8192

__device__ double g_partial[MAXB];
__device__ int    g_done = 0;

__device__ __forceinline__ float fast_lg2(float x) {
    float r; asm("lg2.approx.f32 %0, %1;" : "=f"(r) : "f"(x)); return r;
}
// e = 2^( a XOR signbit(s) ): LOP3 (immLut 0x78 = a^(b&c)) + EX2
__device__ __forceinline__ float ex2s(float a, float s) {
    float r;
    asm("{\n\t"
        ".reg .b32 t;\n\t"
        ".reg .f32 f;\n\t"
        "lop3.b32 t, %1, %2, 0x80000000, 0x78;\n\t"
        "mov.b32 f, t;\n\t"
        "ex2.approx.f32 %0, f;\n\t"
        "}" : "=f"(r) : "r"(__float_as_uint(a)), "r"(__float_as_uint(s)));
    return r;
}
// Band: if (jgx > ig) prod = fma(prod, e, prod)
__device__ __forceinline__ void fma_if_gt(float& prod, float e, int jgx, int ig) {
    asm("{\n\t"
        ".reg .pred p;\n\t"
        "setp.gt.s32 p, %2, %3;\n\t"
        "@p fma.rn.f32 %0, %0, %1, %0;\n\t"
        "}" : "+f"(prod) : "f"(e), "r"(jgx), "r"(ig));
}

// Pair {i,j}: logsig(d) = -ln2 * lg2(1 + 2^arg),
//   arg = (pi - pj)*log2e XOR signbit(ti - tj).  Count analytic: n(n-1)/2.
__global__ __launch_bounds__(THREADS, 4)
void rankloss_kernel(const float* __restrict__ P, const float* __restrict__ T,
                     float* __restrict__ out, int n, int NTI, int NTJ,
                     double inv_neg_count) {
    const int tid = threadIdx.x;
    const int nb  = gridDim.x;

    // decode linear block id -> (I, J) over upper-triangle band
    int b = blockIdx.x, I = 0, J = 0;
    {
        int rem = b;
        for (int ii = 0; ii < NTI; ++ii) {
            int jmin = (ii * I_TILE) / J_TILE;
            int cntI = NTJ - jmin;
            if (rem < cntI) { I = ii; J = jmin + rem; break; }
            rem -= cntI;
        }
    }
    const int I0 = I * I_TILE;
    const int J0 = J * J_TILE;
    const bool dense = (J0 >= I0 + I_TILE) && (J0 + J_TILE <= n) && (I0 + I_TILE <= n);

    __shared__ float2 sj[J_TILE];     // (-tj, -pj*log2e)
    __shared__ double sred[THREADS];

    const float LOG2E = 1.4426950408889634f;

    if (tid < J_TILE) {
        int jg = J0 + tid;
        float2 v;
        if (jg < n) { v.x = -T[jg]; v.y = -(P[jg] * LOG2E); }
        else        { v.x = 0.0f;   v.y = 0.0f; }   // masked structurally in band
        sj[tid] = v;
    }

    float pis[IT], tis[IT];
    int   igv[IT];
    #pragma unroll
    for (int r = 0; r < IT; ++r) {
        int ig = I0 + r * THREADS + tid;
        int g  = (ig < n) ? ig : 0;
        pis[r] = P[g] * LOG2E;
        tis[r] = T[g];
        igv[r] = ig;
    }
    __syncthreads();

    float acc = 0.0f;

    if (dense) {
        #pragma unroll 1
        for (int j = 0; j < J_TILE; j += 8) {
            float prod0 = 1.0f, prod1 = 1.0f, prod2 = 1.0f, prod3 = 1.0f;
            #pragma unroll
            for (int jj = 0; jj < 8; ++jj) {
                float2 v = sj[j + jj];            // broadcast LDS.64
                float s0 = tis[0] + v.x, a0 = pis[0] + v.y;
                float s1 = tis[1] + v.x, a1 = pis[1] + v.y;
                float s2 = tis[2] + v.x, a2 = pis[2] + v.y;
                float s3 = tis[3] + v.x, a3 = pis[3] + v.y;
                float e0 = ex2s(a0, s0);
                float e1 = ex2s(a1, s1);
                float e2 = ex2s(a2, s2);
                float e3 = ex2s(a3, s3);
                prod0 = fmaf(prod0, e0, prod0);
                prod1 = fmaf(prod1, e1, prod1);
                prod2 = fmaf(prod2, e2, prod2);
                prod3 = fmaf(prod3, e3, prod3);
            }
            acc += fast_lg2(prod0);
            acc += fast_lg2(prod1);
            acc += fast_lg2(prod2);
            acc += fast_lg2(prod3);
        }
    } else {
        #pragma unroll 1
        for (int j = 0; j < J_TILE; j += 8) {
            float prod0 = 1.0f, prod1 = 1.0f, prod2 = 1.0f, prod3 = 1.0f;
            #pragma unroll
            for (int jj = 0; jj < 8; ++jj) {
                int jg  = J0 + j + jj;
                int jgx = (jg < n) ? jg : (int)0x80000000;   // never > any ig
                float2 v = sj[j + jj];
                float s0 = tis[0] + v.x, a0 = pis[0] + v.y;
                float s1 = tis[1] + v.x, a1 = pis[1] + v.y;
                float s2 = tis[2] + v.x, a2 = pis[2] + v.y;
                float s3 = tis[3] + v.x, a3 = pis[3] + v.y;
                float e0 = ex2s(a0, s0);
                float e1 = ex2s(a1, s1);
                float e2 = ex2s(a2, s2);
                float e3 = ex2s(a3, s3);
                fma_if_gt(prod0, e0, jgx, igv[0]);
                fma_if_gt(prod1, e1, jgx, igv[1]);
                fma_if_gt(prod2, e2, jgx, igv[2]);
                fma_if_gt(prod3, e3, jgx, igv[3]);
            }
            acc += fast_lg2(prod0);
            acc += fast_lg2(prod1);
            acc += fast_lg2(prod2);
            acc += fast_lg2(prod3);
        }
    }

    // block reduction (fixed order -> deterministic)
    sred[tid] = (double)acc;
    __syncthreads();
    #pragma unroll
    for (int s = THREADS / 2; s > 0; s >>= 1) {
        if (tid < s) sred[tid] += sred[tid + s];
        __syncthreads();
    }
    if (tid == 0) g_partial[blockIdx.x] = sred[0];

    // last-block finalize (fixed order -> deterministic)
    __shared__ int is_last;
    if (tid == 0) {
        __threadfence();
        int prev = atomicAdd(&g_done, 1);
        is_last = (prev == nb - 1) ? 1 : 0;
    }
    __syncthreads();
    if (is_last) {
        __threadfence();
        double s = 0.0;
        for (int i = tid; i < nb; i += THREADS) s += g_partial[i];
        sred[tid] = s;
        __syncthreads();
        #pragma unroll
        for (int k = THREADS / 2; k > 0; k >>= 1) {
            if (tid < k) sred[tid] += sred[tid + k];
            __syncthreads();
        }
        if (tid == 0) {
            out[0] = (float)(sred[0] * inv_neg_count);
            g_done = 0;   // reset for next graph replay
        }
    }
}

extern "C" void kernel_launch(void* const* d_in, const int* in_sizes, int n_in,
                              void* d_out, int out_size) {
    const float* predictions = (const float*)d_in[0];
    const float* targets     = (const float*)d_in[1];
    const int n = in_sizes[0];

    const int NTI = (n + I_TILE - 1) / I_TILE;   // 8 for n=8192
    const int NTJ = (n + J_TILE - 1) / J_TILE;   // 128
    int nb = 0;
    for (int ii = 0; ii < NTI; ++ii) {
        int jmin = (ii * I_TILE) / J_TILE;
        nb += NTJ - jmin;                        // 576 for n=8192
    }
    const double count = 0.5 * (double)n * (double)(n - 1);
    const double inv_neg_count = -0.6931471805599453 / count;

    rankloss_kernel<<<nb, THREADS>>>(predictions, targets, (float*)d_out,
                                     n, NTI, NTJ, inv_neg_count);
}